// round 6
// baseline (speedup 1.0000x reference)
#include <cuda_runtime.h>
#include <cuda_bf16.h>
#include <math.h>
#include <stdint.h>

#define SDIM 4096
#define BDIM 4096
#define BM 128
#define BN 128
#define BK 32
#define NCH (SDIM / BK)      // 128
#define NTILE (SDIM / BN)    // 32
#define NSTAGE 4
#define STGB 32768           // bytes per stage: Ah 8K, Al 8K, Bh 8K, Bl 8K

// ---------------- scratch ----------------
__device__ float g_c[SDIM];
__device__ float g_d[SDIM];
__device__ float g_partial[(size_t)BDIM * NTILE];
__device__ __nv_bfloat16 g_xh[(size_t)BDIM * SDIM];
__device__ __nv_bfloat16 g_xl[(size_t)BDIM * SDIM];
__device__ __nv_bfloat16 g_wh[(size_t)SDIM * SDIM];
__device__ __nv_bfloat16 g_wl[(size_t)SDIM * SDIM];

// ---------------- helpers ----------------
__device__ __forceinline__ float gelu_exact(float x) {
    return 0.5f * x * (1.0f + erff(x * 0.70710678118654752f));
}

__device__ __forceinline__ uint32_t smem_u32(const void* p) {
    uint32_t a;
    asm("{ .reg .u64 t; cvta.to.shared.u64 t, %1; cvt.u32.u64 %0, t; }" : "=r"(a) : "l"(p));
    return a;
}

// swizzle for 64B rows: XOR 16B-column bits [5:4] with row bits (off bits [8:7])
__device__ __forceinline__ uint32_t swz(uint32_t off) {
    return off ^ ((off >> 3) & 0x30);
}

#define CP_ASYNC_16(dst, src) \
    asm volatile("cp.async.cg.shared.global [%0], [%1], 16;" :: "r"(dst), "l"(src))
#define CP_COMMIT() asm volatile("cp.async.commit_group;" ::: "memory")
#define CP_WAIT(n)  asm volatile("cp.async.wait_group %0;" :: "n"(n) : "memory")

#define LDSM_X4(r0, r1, r2, r3, addr) \
    asm volatile("ldmatrix.sync.aligned.m8n8.x4.shared.b16 {%0,%1,%2,%3}, [%4];" \
        : "=r"(r0), "=r"(r1), "=r"(r2), "=r"(r3) : "r"(addr))

__device__ __forceinline__ void mma16816(float* c, uint32_t a0, uint32_t a1, uint32_t a2, uint32_t a3,
                                         uint32_t b0, uint32_t b1) {
    asm volatile("mma.sync.aligned.m16n8k16.row.col.f32.bf16.bf16.f32 "
        "{%0,%1,%2,%3}, {%4,%5,%6,%7}, {%8,%9}, {%0,%1,%2,%3};"
        : "+f"(c[0]), "+f"(c[1]), "+f"(c[2]), "+f"(c[3])
        : "r"(a0), "r"(a1), "r"(a2), "r"(a3), "r"(b0), "r"(b1));
}

__device__ __forceinline__ uint32_t pack_bf16(__nv_bfloat16 a, __nv_bfloat16 b) {
    return (uint32_t)__bfloat16_as_ushort(a) | ((uint32_t)__bfloat16_as_ushort(b) << 16);
}

// ---------------- conversion kernel: fp32 -> bf16 hi/lo ----------------
__global__ void convert_kernel(const float* __restrict__ src,
                               __nv_bfloat16* __restrict__ dh,
                               __nv_bfloat16* __restrict__ dl) {
    size_t i = ((size_t)blockIdx.x * blockDim.x + threadIdx.x) * 4;
    float4 v = *(const float4*)(src + i);
    __nv_bfloat16 h0 = __float2bfloat16_rn(v.x), h1 = __float2bfloat16_rn(v.y);
    __nv_bfloat16 h2 = __float2bfloat16_rn(v.z), h3 = __float2bfloat16_rn(v.w);
    __nv_bfloat16 l0 = __float2bfloat16_rn(v.x - __bfloat162float(h0));
    __nv_bfloat16 l1 = __float2bfloat16_rn(v.y - __bfloat162float(h1));
    __nv_bfloat16 l2 = __float2bfloat16_rn(v.z - __bfloat162float(h2));
    __nv_bfloat16 l3 = __float2bfloat16_rn(v.w - __bfloat162float(h3));
    *(uint2*)(dh + i) = make_uint2(pack_bf16(h0, h1), pack_bf16(h2, h3));
    *(uint2*)(dl + i) = make_uint2(pack_bf16(l0, l1), pack_bf16(l2, l3));
}

// ---------------- prologue kernels ----------------
__device__ __forceinline__ float block_reduce_sum(float v, float* sbuf) {
    int lane = threadIdx.x & 31, warp = threadIdx.x >> 5;
    #pragma unroll
    for (int o = 16; o > 0; o >>= 1) v += __shfl_down_sync(0xffffffffu, v, o);
    if (lane == 0) sbuf[warp] = v;
    __syncthreads();
    if (warp == 0) {
        v = (lane < ((int)blockDim.x >> 5)) ? sbuf[lane] : 0.0f;
        #pragma unroll
        for (int o = 16; o > 0; o >>= 1) v += __shfl_down_sync(0xffffffffu, v, o);
    }
    return v;
}

__global__ void compute_c_kernel(const float* __restrict__ sgu_proj_w,
                                 const float* __restrict__ sgu_proj_b,
                                 const float* __restrict__ ln1_b,
                                 const float* __restrict__ cp1_w,
                                 const float* __restrict__ cp1_b,
                                 const float* __restrict__ sgu_ln_b,
                                 const float* __restrict__ cp2_w,
                                 const float* __restrict__ cp2_b) {
    __shared__ float sbuf[8];
    int s = blockIdx.x;
    float total = 0.0f;
    #pragma unroll
    for (int i = 0; i < 2; ++i) {
        const float* row = sgu_proj_w + (size_t)i * SDIM * SDIM + (size_t)s * SDIM;
        float acc = 0.0f;
        for (int t = threadIdx.x * 4; t < SDIM; t += blockDim.x * 4) {
            float4 v = *(const float4*)(row + t);
            acc += (v.x + v.y) + (v.z + v.w);
        }
        float rowsum = block_reduce_sum(acc, sbuf);
        if (threadIdx.x == 0) {
            float tln = ln1_b[i];  // LN over size-1 axis == bias
            float Gu  = gelu_exact(tln * cp1_w[i * 2 + 0] + cp1_b[i * 2 + 0]);
            float vp  = sgu_ln_b[i] * rowsum + sgu_proj_b[(size_t)i * SDIM + s];
            total += (Gu * vp) * cp2_w[i] + cp2_b[i];
        }
        __syncthreads();
    }
    if (threadIdx.x == 0) g_c[s] = total;
}

__global__ void compute_d_kernel(const float* __restrict__ pooler_w,
                                 const float* __restrict__ pooler_b) {
    __shared__ float sbuf[8];
    int sp = blockIdx.x;
    const float* row = pooler_w + (size_t)sp * SDIM;
    float acc = 0.0f;
    for (int t = threadIdx.x * 4; t < SDIM; t += blockDim.x * 4) {
        float4 v = *(const float4*)(row + t);
        acc += v.x * g_c[t] + v.y * g_c[t + 1] + v.z * g_c[t + 2] + v.w * g_c[t + 3];
    }
    float v = block_reduce_sum(acc, sbuf);
    if (threadIdx.x == 0) g_d[sp] = v + pooler_b[sp];
}

// ---------------- bf16 3-split GEMM, cp.async 4-stage pipeline ----------------
// stage layout: Ah @0, Al @8192, Bh @16384, Bl @24576  (each 128 rows x 64B, swizzled)
__global__ void __launch_bounds__(256)
gemm_hmma_kernel(const float* __restrict__ clsw) {
    extern __shared__ __align__(1024) char smem[];
    const uint32_t sb = smem_u32(smem);

    const int tid  = threadIdx.x;
    const int lane = tid & 31;
    const int wid  = tid >> 5;
    const int g    = lane >> 2;
    const int t4   = lane & 3;
    const int wm   = (wid & 3) * 32;
    const int wn   = (wid >> 2) * 64;
    const int bB   = blockIdx.y * BM;
    const int bS   = blockIdx.x * BN;

    // producer: 2 16B-atoms per buffer per thread
    const int a0 = tid * 2, a1 = tid * 2 + 1;
    const int r0 = a0 >> 2, c0 = a0 & 3;
    const int r1 = a1 >> 2, c1 = a1 & 3;
    const __nv_bfloat16* pxh0 = g_xh + (size_t)(bB + r0) * SDIM + c0 * 8;
    const __nv_bfloat16* pxh1 = g_xh + (size_t)(bB + r1) * SDIM + c1 * 8;
    const __nv_bfloat16* pxl0 = g_xl + (size_t)(bB + r0) * SDIM + c0 * 8;
    const __nv_bfloat16* pxl1 = g_xl + (size_t)(bB + r1) * SDIM + c1 * 8;
    const __nv_bfloat16* pwh0 = g_wh + (size_t)(bS + r0) * SDIM + c0 * 8;
    const __nv_bfloat16* pwh1 = g_wh + (size_t)(bS + r1) * SDIM + c1 * 8;
    const __nv_bfloat16* pwl0 = g_wl + (size_t)(bS + r0) * SDIM + c0 * 8;
    const __nv_bfloat16* pwl1 = g_wl + (size_t)(bS + r1) * SDIM + c1 * 8;
    const uint32_t d0 = swz((uint32_t)(r0 * 64 + c0 * 16));
    const uint32_t d1 = swz((uint32_t)(r1 * 64 + c1 * 16));

    // ldmatrix fragment offsets: kb*32 folded in PRE-swizzle (bit 5 clean, no carry)
    uint32_t offAm[2][2], offBn[4][2];
    {
        int r = lane & 15, kc = lane >> 4;
        #pragma unroll
        for (int mt = 0; mt < 2; ++mt)
            #pragma unroll
            for (int kb = 0; kb < 2; ++kb)
                offAm[mt][kb] = swz((uint32_t)((wm + mt * 16 + r) * 64 + kc * 16 + kb * 32));
        int rb = (lane & 7) + ((lane >> 4) << 3), kcb = (lane >> 3) & 1;
        #pragma unroll
        for (int np = 0; np < 4; ++np)
            #pragma unroll
            for (int kb = 0; kb < 2; ++kb)
                offBn[np][kb] = swz((uint32_t)((wn + np * 16 + rb) * 64 + kcb * 16 + kb * 32));
    }

    float acc[2][8][4];
    #pragma unroll
    for (int mt = 0; mt < 2; ++mt)
        #pragma unroll
        for (int nt = 0; nt < 8; ++nt)
            #pragma unroll
            for (int c = 0; c < 4; ++c) acc[mt][nt][c] = 0.0f;

    // issue loads for one stage
    auto issue = [&](int stage, int ch) {
        const uint32_t stb = sb + stage * STGB;
        const int ko = ch * BK;
        CP_ASYNC_16(stb + d0,         (const char*)(pxh0 + ko));
        CP_ASYNC_16(stb + d1,         (const char*)(pxh1 + ko));
        CP_ASYNC_16(stb + 8192 + d0,  (const char*)(pxl0 + ko));
        CP_ASYNC_16(stb + 8192 + d1,  (const char*)(pxl1 + ko));
        CP_ASYNC_16(stb + 16384 + d0, (const char*)(pwh0 + ko));
        CP_ASYNC_16(stb + 16384 + d1, (const char*)(pwh1 + ko));
        CP_ASYNC_16(stb + 24576 + d0, (const char*)(pwl0 + ko));
        CP_ASYNC_16(stb + 24576 + d1, (const char*)(pwl1 + ko));
    };

    // prologue: stages 0..2
    #pragma unroll
    for (int s = 0; s < NSTAGE - 1; ++s) { issue(s, s); CP_COMMIT(); }

    #pragma unroll 1
    for (int ch = 0; ch < NCH; ++ch) {
        CP_WAIT(NSTAGE - 2);   // stage ch complete
        __syncthreads();       // also: all reads of stage (ch-1)%4 finished

        // issue next stage (empty commit keeps group bookkeeping uniform)
        if (ch + NSTAGE - 1 < NCH) issue((ch + NSTAGE - 1) & (NSTAGE - 1), ch + NSTAGE - 1);
        CP_COMMIT();

        const uint32_t stb = sb + (ch & (NSTAGE - 1)) * STGB;
        #pragma unroll
        for (int kb = 0; kb < 2; ++kb) {
            uint32_t aH[2][4], aL[2][4];
            #pragma unroll
            for (int mt = 0; mt < 2; ++mt) {
                LDSM_X4(aH[mt][0], aH[mt][1], aH[mt][2], aH[mt][3], stb + offAm[mt][kb]);
                LDSM_X4(aL[mt][0], aL[mt][1], aL[mt][2], aL[mt][3], stb + 8192 + offAm[mt][kb]);
            }
            #pragma unroll
            for (int np = 0; np < 4; ++np) {
                uint32_t bH[4], bL[4];
                LDSM_X4(bH[0], bH[1], bH[2], bH[3], stb + 16384 + offBn[np][kb]);
                LDSM_X4(bL[0], bL[1], bL[2], bL[3], stb + 24576 + offBn[np][kb]);
                #pragma unroll
                for (int mt = 0; mt < 2; ++mt) {
                    #pragma unroll
                    for (int j = 0; j < 2; ++j) {
                        float* c = acc[mt][np * 2 + j];
                        mma16816(c, aH[mt][0], aH[mt][1], aH[mt][2], aH[mt][3], bH[2*j], bH[2*j+1]);
                        mma16816(c, aH[mt][0], aH[mt][1], aH[mt][2], aH[mt][3], bL[2*j], bL[2*j+1]);
                        mma16816(c, aL[mt][0], aL[mt][1], aL[mt][2], aL[mt][3], bH[2*j], bH[2*j+1]);
                    }
                }
            }
        }
    }

    // ---------------- fused epilogue ----------------
    CP_WAIT(0);
    float rs[4] = {0.0f, 0.0f, 0.0f, 0.0f};
    #pragma unroll
    for (int nt = 0; nt < 8; ++nt) {
        int col0 = bS + wn + nt * 8 + 2 * t4;
        float dd0 = g_d[col0],     w0 = clsw[col0];
        float dd1 = g_d[col0 + 1], w1 = clsw[col0 + 1];
        #pragma unroll
        for (int mt = 0; mt < 2; ++mt) {
            rs[mt * 2 + 0] += gelu_exact(acc[mt][nt][0] + dd0) * w0
                            + gelu_exact(acc[mt][nt][1] + dd1) * w1;
            rs[mt * 2 + 1] += gelu_exact(acc[mt][nt][2] + dd0) * w0
                            + gelu_exact(acc[mt][nt][3] + dd1) * w1;
        }
    }
    #pragma unroll
    for (int o = 1; o <= 2; o <<= 1) {
        #pragma unroll
        for (int i = 0; i < 4; ++i) rs[i] += __shfl_xor_sync(0xffffffffu, rs[i], o);
    }

    float* redbuf = (float*)smem;   // [2][128]
    __syncthreads();
    if (t4 == 0) {
        #pragma unroll
        for (int mt = 0; mt < 2; ++mt)
            #pragma unroll
            for (int h = 0; h < 2; ++h) {
                int row = wm + mt * 16 + h * 8 + g;
                redbuf[(wid >> 2) * 128 + row] = rs[mt * 2 + h];
            }
    }
    __syncthreads();
    if (tid < 128) {
        float p = redbuf[tid] + redbuf[128 + tid];
        g_partial[(size_t)(bB + tid) * NTILE + blockIdx.x] = p;
    }
}

__global__ void final_kernel(const float* __restrict__ cls_b, float* __restrict__ out) {
    int b = blockIdx.x * blockDim.x + threadIdx.x;
    if (b < BDIM) {
        float sum = 0.0f;
        #pragma unroll
        for (int j = 0; j < NTILE; ++j) sum += g_partial[(size_t)b * NTILE + j];
        out[b] = sum + cls_b[0];
    }
}

// ---------------- launch ----------------
extern "C" void kernel_launch(void* const* d_in, const int* in_sizes, int n_in,
                              void* d_out, int out_size) {
    const float* x          = (const float*)d_in[0];
    const float* ln1_b      = (const float*)d_in[2];
    const float* cp1_w      = (const float*)d_in[3];
    const float* cp1_b      = (const float*)d_in[4];
    const float* sgu_ln_b   = (const float*)d_in[6];
    const float* sgu_proj_w = (const float*)d_in[7];
    const float* sgu_proj_b = (const float*)d_in[8];
    const float* cp2_w      = (const float*)d_in[9];
    const float* cp2_b      = (const float*)d_in[10];
    const float* pooler_w   = (const float*)d_in[11];
    const float* pooler_b   = (const float*)d_in[12];
    const float* cls_w      = (const float*)d_in[13];
    const float* cls_b      = (const float*)d_in[14];

    cudaFuncSetAttribute(gemm_hmma_kernel, cudaFuncAttributeMaxDynamicSharedMemorySize,
                         NSTAGE * STGB);

    __nv_bfloat16 *xh, *xl, *wh, *wl;
    cudaGetSymbolAddress((void**)&xh, g_xh);
    cudaGetSymbolAddress((void**)&xl, g_xl);
    cudaGetSymbolAddress((void**)&wh, g_wh);
    cudaGetSymbolAddress((void**)&wl, g_wl);

    convert_kernel<<<(size_t)BDIM * SDIM / 1024, 256>>>(x, xh, xl);
    convert_kernel<<<(size_t)SDIM * SDIM / 1024, 256>>>(pooler_w, wh, wl);

    compute_c_kernel<<<SDIM, 256>>>(sgu_proj_w, sgu_proj_b, ln1_b, cp1_w, cp1_b,
                                    sgu_ln_b, cp2_w, cp2_b);
    compute_d_kernel<<<SDIM, 256>>>(pooler_w, pooler_b);

    dim3 grid(SDIM / BN, BDIM / BM);   // (32, 32)
    gemm_hmma_kernel<<<grid, 256, NSTAGE * STGB>>>(cls_w);

    final_kernel<<<(BDIM + 255) / 256, 256>>>(cls_b, (float*)d_out);
}

// round 9
// speedup vs baseline: 1.7462x; 1.7462x over previous
#include <cuda_runtime.h>
#include <cuda_bf16.h>
#include <math.h>
#include <stdint.h>

#define SDIM 4096
#define BDIM 4096
#define BM 128
#define BN 128
#define BK 32
#define NCH (SDIM / BK)      // 128
#define NTILE (SDIM / BN)    // 32
#define NSTAGE 3
#define STGB 32768           // per stage: Ah 8K, Al 8K, Bh 8K, Bl 8K

// ---------------- scratch ----------------
__device__ float g_c[SDIM];
__device__ float g_d[SDIM];
__device__ float g_partial[(size_t)BDIM * NTILE];
// interleaved hi/lo: row r occupies 8192 bf16; [0,4096)=hi, [4096,8192)=lo
__device__ __nv_bfloat16 g_xs[(size_t)BDIM * 8192];
__device__ __nv_bfloat16 g_ws[(size_t)SDIM * 8192];

// ---------------- helpers ----------------
__device__ __forceinline__ float gelu_exact(float x) {
    return 0.5f * x * (1.0f + erff(x * 0.70710678118654752f));
}

__device__ __forceinline__ uint32_t smem_u32(const void* p) {
    uint32_t a;
    asm("{ .reg .u64 t; cvta.to.shared.u64 t, %1; cvt.u32.u64 %0, t; }" : "=r"(a) : "l"(p));
    return a;
}

// swizzle for 64B rows: XOR byte bits [5:4] with row bits [2:1] (off bits [8:7])
__device__ __forceinline__ uint32_t swz(uint32_t off) {
    return off ^ ((off >> 3) & 0x30);
}

#define CP_ASYNC_16(dst, src) \
    asm volatile("cp.async.cg.shared.global [%0], [%1], 16;" :: "r"(dst), "l"(src))
#define CP_COMMIT() asm volatile("cp.async.commit_group;" ::: "memory")
#define CP_WAIT(n)  asm volatile("cp.async.wait_group %0;" :: "n"(n) : "memory")

#define LDSM_X4(r0, r1, r2, r3, addr) \
    asm volatile("ldmatrix.sync.aligned.m8n8.x4.shared.b16 {%0,%1,%2,%3}, [%4];" \
        : "=r"(r0), "=r"(r1), "=r"(r2), "=r"(r3) : "r"(addr))

__device__ __forceinline__ void mma16816(float* c, uint32_t a0, uint32_t a1, uint32_t a2, uint32_t a3,
                                         uint32_t b0, uint32_t b1) {
    asm volatile("mma.sync.aligned.m16n8k16.row.col.f32.bf16.bf16.f32 "
        "{%0,%1,%2,%3}, {%4,%5,%6,%7}, {%8,%9}, {%0,%1,%2,%3};"
        : "+f"(c[0]), "+f"(c[1]), "+f"(c[2]), "+f"(c[3])
        : "r"(a0), "r"(a1), "r"(a2), "r"(a3), "r"(b0), "r"(b1));
}

__device__ __forceinline__ uint32_t pack_bf16(__nv_bfloat16 a, __nv_bfloat16 b) {
    return (uint32_t)__bfloat16_as_ushort(a) | ((uint32_t)__bfloat16_as_ushort(b) << 16);
}

// ---------------- conversion: fp32 -> interleaved bf16 hi/lo ----------------
__global__ void convert_kernel(const float* __restrict__ src,
                               __nv_bfloat16* __restrict__ dst) {
    size_t i = ((size_t)blockIdx.x * blockDim.x + threadIdx.x) * 4;
    size_t row = i >> 12;           // /4096
    size_t col = i & 4095;
    float4 v = *(const float4*)(src + i);
    __nv_bfloat16 h0 = __float2bfloat16_rn(v.x), h1 = __float2bfloat16_rn(v.y);
    __nv_bfloat16 h2 = __float2bfloat16_rn(v.z), h3 = __float2bfloat16_rn(v.w);
    __nv_bfloat16 l0 = __float2bfloat16_rn(v.x - __bfloat162float(h0));
    __nv_bfloat16 l1 = __float2bfloat16_rn(v.y - __bfloat162float(h1));
    __nv_bfloat16 l2 = __float2bfloat16_rn(v.z - __bfloat162float(h2));
    __nv_bfloat16 l3 = __float2bfloat16_rn(v.w - __bfloat162float(h3));
    size_t base = row * 8192 + col;
    *(uint2*)(dst + base)        = make_uint2(pack_bf16(h0, h1), pack_bf16(h2, h3));
    *(uint2*)(dst + base + 4096) = make_uint2(pack_bf16(l0, l1), pack_bf16(l2, l3));
}

// ---------------- prologue kernels ----------------
__device__ __forceinline__ float block_reduce_sum(float v, float* sbuf) {
    int lane = threadIdx.x & 31, warp = threadIdx.x >> 5;
    #pragma unroll
    for (int o = 16; o > 0; o >>= 1) v += __shfl_down_sync(0xffffffffu, v, o);
    if (lane == 0) sbuf[warp] = v;
    __syncthreads();
    if (warp == 0) {
        v = (lane < ((int)blockDim.x >> 5)) ? sbuf[lane] : 0.0f;
        #pragma unroll
        for (int o = 16; o > 0; o >>= 1) v += __shfl_down_sync(0xffffffffu, v, o);
    }
    return v;
}

__global__ void compute_c_kernel(const float* __restrict__ sgu_proj_w,
                                 const float* __restrict__ sgu_proj_b,
                                 const float* __restrict__ ln1_b,
                                 const float* __restrict__ cp1_w,
                                 const float* __restrict__ cp1_b,
                                 const float* __restrict__ sgu_ln_b,
                                 const float* __restrict__ cp2_w,
                                 const float* __restrict__ cp2_b) {
    __shared__ float sbuf[8];
    int s = blockIdx.x;
    float total = 0.0f;
    #pragma unroll
    for (int i = 0; i < 2; ++i) {
        const float* row = sgu_proj_w + (size_t)i * SDIM * SDIM + (size_t)s * SDIM;
        float acc = 0.0f;
        for (int t = threadIdx.x * 4; t < SDIM; t += blockDim.x * 4) {
            float4 v = *(const float4*)(row + t);
            acc += (v.x + v.y) + (v.z + v.w);
        }
        float rowsum = block_reduce_sum(acc, sbuf);
        if (threadIdx.x == 0) {
            float tln = ln1_b[i];  // LN over size-1 axis == bias
            float Gu  = gelu_exact(tln * cp1_w[i * 2 + 0] + cp1_b[i * 2 + 0]);
            float vp  = sgu_ln_b[i] * rowsum + sgu_proj_b[(size_t)i * SDIM + s];
            total += (Gu * vp) * cp2_w[i] + cp2_b[i];
        }
        __syncthreads();
    }
    if (threadIdx.x == 0) g_c[s] = total;
}

__global__ void compute_d_kernel(const float* __restrict__ pooler_w,
                                 const float* __restrict__ pooler_b) {
    __shared__ float sbuf[8];
    int sp = blockIdx.x;
    const float* row = pooler_w + (size_t)sp * SDIM;
    float acc = 0.0f;
    for (int t = threadIdx.x * 4; t < SDIM; t += blockDim.x * 4) {
        float4 v = *(const float4*)(row + t);
        acc += v.x * g_c[t] + v.y * g_c[t + 1] + v.z * g_c[t + 2] + v.w * g_c[t + 3];
    }
    float v = block_reduce_sum(acc, sbuf);
    if (threadIdx.x == 0) g_d[sp] = v + pooler_b[sp];
}

// ---------------- bf16 3-split GEMM, cp.async 3-stage, occ 2 ----------------
// stage layout: Ah @0, Al @8192, Bh @16384, Bl @24576  (each 128 rows x 64B, swizzled)
__global__ void __launch_bounds__(256, 2)
gemm_hmma_kernel(const float* __restrict__ clsw) {
    extern __shared__ __align__(1024) char smem[];
    const uint32_t sb = smem_u32(smem);

    const int tid  = threadIdx.x;
    const int lane = tid & 31;
    const int wid  = tid >> 5;
    const int g    = lane >> 2;
    const int t4   = lane & 3;
    const int wm   = (wid & 3) * 32;
    const int wn   = (wid >> 2) * 64;
    const int bB   = blockIdx.y * BM;
    const int bS   = blockIdx.x * BN;

    // producer: thread -> row = tid/2, byte-col (tid&1)*32 within 64B row (two 16B atoms)
    const int prow = tid >> 1;
    const int pcb  = (tid & 1) * 32;
    const char* XB = (const char*)g_xs + (size_t)(bB + prow) * 16384 + pcb;
    const char* WB = (const char*)g_ws + (size_t)(bS + prow) * 16384 + pcb;
    const uint32_t d0 = swz((uint32_t)(prow * 64 + pcb));
    const uint32_t d1 = swz((uint32_t)(prow * 64 + pcb + 16));

    // ldmatrix fragment offsets: kb*32 folded PRE-swizzle
    uint32_t offAm[2][2], offBn[4][2];
    {
        int r = lane & 15, kc = lane >> 4;
        #pragma unroll
        for (int mt = 0; mt < 2; ++mt)
            #pragma unroll
            for (int kb = 0; kb < 2; ++kb)
                offAm[mt][kb] = swz((uint32_t)((wm + mt * 16 + r) * 64 + kc * 16 + kb * 32));
        int rb = (lane & 7) + ((lane >> 4) << 3), kcb = (lane >> 3) & 1;
        #pragma unroll
        for (int np = 0; np < 4; ++np)
            #pragma unroll
            for (int kb = 0; kb < 2; ++kb)
                offBn[np][kb] = swz((uint32_t)((wn + np * 16 + rb) * 64 + kcb * 16 + kb * 32));
    }

    float acc[2][8][4];
    #pragma unroll
    for (int mt = 0; mt < 2; ++mt)
        #pragma unroll
        for (int nt = 0; nt < 8; ++nt)
            #pragma unroll
            for (int c = 0; c < 4; ++c) acc[mt][nt][c] = 0.0f;

    // issue one stage's loads: 8 x 16B per thread
    auto issue = [&](int stage, int ch) {
        const uint32_t stb = sb + stage * STGB;
        const int ko2 = ch * (BK * 2);       // byte offset in hi half
        CP_ASYNC_16(stb + d0,         XB + ko2);
        CP_ASYNC_16(stb + d1,         XB + ko2 + 16);
        CP_ASYNC_16(stb + 8192 + d0,  XB + 8192 + ko2);
        CP_ASYNC_16(stb + 8192 + d1,  XB + 8192 + ko2 + 16);
        CP_ASYNC_16(stb + 16384 + d0, WB + ko2);
        CP_ASYNC_16(stb + 16384 + d1, WB + ko2 + 16);
        CP_ASYNC_16(stb + 24576 + d0, WB + 8192 + ko2);
        CP_ASYNC_16(stb + 24576 + d1, WB + 8192 + ko2 + 16);
    };

    // prologue: stages 0..NSTAGE-2
    #pragma unroll
    for (int s = 0; s < NSTAGE - 1; ++s) { issue(s, s); CP_COMMIT(); }

    int rd = 0, wr = NSTAGE - 1;
    #pragma unroll 1
    for (int ch = 0; ch < NCH; ++ch) {
        CP_WAIT(NSTAGE - 2);   // stage for chunk ch complete
        __syncthreads();       // + all reads of the stage we are about to overwrite done

        if (ch + NSTAGE - 1 < NCH) issue(wr, ch + NSTAGE - 1);
        CP_COMMIT();           // (possibly empty group — keeps bookkeeping uniform)
        if (++wr == NSTAGE) wr = 0;

        const uint32_t stb = sb + rd * STGB;
        if (++rd == NSTAGE) rd = 0;
        #pragma unroll
        for (int kb = 0; kb < 2; ++kb) {
            uint32_t aH[2][4], aL[2][4];
            #pragma unroll
            for (int mt = 0; mt < 2; ++mt) {
                LDSM_X4(aH[mt][0], aH[mt][1], aH[mt][2], aH[mt][3], stb + offAm[mt][kb]);
                LDSM_X4(aL[mt][0], aL[mt][1], aL[mt][2], aL[mt][3], stb + 8192 + offAm[mt][kb]);
            }
            #pragma unroll
            for (int np = 0; np < 4; ++np) {
                uint32_t bH[4], bL[4];
                LDSM_X4(bH[0], bH[1], bH[2], bH[3], stb + 16384 + offBn[np][kb]);
                LDSM_X4(bL[0], bL[1], bL[2], bL[3], stb + 24576 + offBn[np][kb]);
                #pragma unroll
                for (int mt = 0; mt < 2; ++mt) {
                    #pragma unroll
                    for (int j = 0; j < 2; ++j) {
                        float* c = acc[mt][np * 2 + j];
                        mma16816(c, aH[mt][0], aH[mt][1], aH[mt][2], aH[mt][3], bH[2*j], bH[2*j+1]);
                        mma16816(c, aH[mt][0], aH[mt][1], aH[mt][2], aH[mt][3], bL[2*j], bL[2*j+1]);
                        mma16816(c, aL[mt][0], aL[mt][1], aL[mt][2], aL[mt][3], bH[2*j], bH[2*j+1]);
                    }
                }
            }
        }
    }

    // ---------------- fused epilogue ----------------
    CP_WAIT(0);
    float rs[4] = {0.0f, 0.0f, 0.0f, 0.0f};
    #pragma unroll
    for (int nt = 0; nt < 8; ++nt) {
        int col0 = bS + wn + nt * 8 + 2 * t4;
        float dd0 = g_d[col0],     w0 = clsw[col0];
        float dd1 = g_d[col0 + 1], w1 = clsw[col0 + 1];
        #pragma unroll
        for (int mt = 0; mt < 2; ++mt) {
            rs[mt * 2 + 0] += gelu_exact(acc[mt][nt][0] + dd0) * w0
                            + gelu_exact(acc[mt][nt][1] + dd1) * w1;
            rs[mt * 2 + 1] += gelu_exact(acc[mt][nt][2] + dd0) * w0
                            + gelu_exact(acc[mt][nt][3] + dd1) * w1;
        }
    }
    #pragma unroll
    for (int o = 1; o <= 2; o <<= 1) {
        #pragma unroll
        for (int i = 0; i < 4; ++i) rs[i] += __shfl_xor_sync(0xffffffffu, rs[i], o);
    }

    float* redbuf = (float*)smem;   // [2][128]
    __syncthreads();
    if (t4 == 0) {
        #pragma unroll
        for (int mt = 0; mt < 2; ++mt)
            #pragma unroll
            for (int h = 0; h < 2; ++h) {
                int row = wm + mt * 16 + h * 8 + g;
                redbuf[(wid >> 2) * 128 + row] = rs[mt * 2 + h];
            }
    }
    __syncthreads();
    if (tid < 128) {
        float p = redbuf[tid] + redbuf[128 + tid];
        g_partial[(size_t)(bB + tid) * NTILE + blockIdx.x] = p;
    }
}

__global__ void final_kernel(const float* __restrict__ cls_b, float* __restrict__ out) {
    int b = blockIdx.x * blockDim.x + threadIdx.x;
    if (b < BDIM) {
        float sum = 0.0f;
        #pragma unroll
        for (int j = 0; j < NTILE; ++j) sum += g_partial[(size_t)b * NTILE + j];
        out[b] = sum + cls_b[0];
    }
}

// ---------------- launch ----------------
extern "C" void kernel_launch(void* const* d_in, const int* in_sizes, int n_in,
                              void* d_out, int out_size) {
    const float* x          = (const float*)d_in[0];
    const float* ln1_b      = (const float*)d_in[2];
    const float* cp1_w      = (const float*)d_in[3];
    const float* cp1_b      = (const float*)d_in[4];
    const float* sgu_ln_b   = (const float*)d_in[6];
    const float* sgu_proj_w = (const float*)d_in[7];
    const float* sgu_proj_b = (const float*)d_in[8];
    const float* cp2_w      = (const float*)d_in[9];
    const float* cp2_b      = (const float*)d_in[10];
    const float* pooler_w   = (const float*)d_in[11];
    const float* pooler_b   = (const float*)d_in[12];
    const float* cls_w      = (const float*)d_in[13];
    const float* cls_b      = (const float*)d_in[14];

    cudaFuncSetAttribute(gemm_hmma_kernel, cudaFuncAttributeMaxDynamicSharedMemorySize,
                         NSTAGE * STGB);

    __nv_bfloat16 *xs, *ws;
    cudaGetSymbolAddress((void**)&xs, g_xs);
    cudaGetSymbolAddress((void**)&ws, g_ws);

    convert_kernel<<<(size_t)BDIM * SDIM / 1024, 256>>>(x, xs);
    convert_kernel<<<(size_t)SDIM * SDIM / 1024, 256>>>(pooler_w, ws);

    compute_c_kernel<<<SDIM, 256>>>(sgu_proj_w, sgu_proj_b, ln1_b, cp1_w, cp1_b,
                                    sgu_ln_b, cp2_w, cp2_b);
    compute_d_kernel<<<SDIM, 256>>>(pooler_w, pooler_b);

    dim3 grid(SDIM / BN, BDIM / BM);   // (32, 32)
    gemm_hmma_kernel<<<grid, 256, NSTAGE * STGB>>>(cls_w);

    final_kernel<<<(BDIM + 255) / 256, 256>>>(cls_b, (float*)d_out);
}